// round 13
// baseline (speedup 1.0000x reference)
#include <cuda_runtime.h>
#include <cuda_bf16.h>
#include <cuda_fp16.h>
#include <cstdint>
#include <math.h>

// Problem constants
#define B_  2
#define T_  2048
#define E_  2048
#define H_  32
#define HKV_ 8
#define D_  64
#define BT_ (B_*T_)  // 4096
#define NQKV 3072    // 2048 Q + 512 K + 512 V

// scale * log2(e): folded into Q at projection time; attention uses ex2 directly
#define QSCALE 0.1803368801111357f   // 0.125 * 1.4426950408889634

// ---------------------------------------------------------------------------
// Scratch (static device globals — allocation-free rule)
// ---------------------------------------------------------------------------
__device__ __half g_xf[BT_ * E_];               // x in fp16
__device__ __half g_Qf[BT_ * H_ * D_];          // post-rope, pre-scaled Q fp16
__device__ __half g_Kf[BT_ * HKV_ * D_];        // post-rope K fp16
__device__ __half g_Vf[BT_ * HKV_ * D_];
__device__ __half g_Yf[BT_ * E_];               // attention output fp16
__device__ __half g_Wcf[NQKV * E_];             // concat Wq|Wk|Wv transposed [N,K] fp16
__device__ __half g_Wof[E_ * E_];               // Wo transposed fp16
__device__ float2 g_tab[T_ * 32];               // rope cos/sin table

// ---------------------------------------------------------------------------
// PTX helpers
// ---------------------------------------------------------------------------
__device__ __forceinline__ uint32_t smem_u32(const void* p) {
    uint32_t a;
    asm("{ .reg .u64 t; cvta.to.shared.u64 t, %1; cvt.u32.u64 %0, t; }" : "=r"(a) : "l"(p));
    return a;
}
__device__ __forceinline__ void ldmx4(uint32_t* r, uint32_t addr) {
    asm volatile("ldmatrix.sync.aligned.m8n8.x4.shared.b16 {%0,%1,%2,%3}, [%4];"
                 : "=r"(r[0]), "=r"(r[1]), "=r"(r[2]), "=r"(r[3]) : "r"(addr));
}
__device__ __forceinline__ void ldmx4t(uint32_t* r, uint32_t addr) {
    asm volatile("ldmatrix.sync.aligned.m8n8.x4.trans.shared.b16 {%0,%1,%2,%3}, [%4];"
                 : "=r"(r[0]), "=r"(r[1]), "=r"(r[2]), "=r"(r[3]) : "r"(addr));
}
__device__ __forceinline__ void mma_f16(float* acc, const uint32_t* a, const uint32_t b0,
                                        const uint32_t b1) {
    asm volatile(
        "mma.sync.aligned.m16n8k16.row.col.f32.f16.f16.f32 "
        "{%0,%1,%2,%3}, {%4,%5,%6,%7}, {%8,%9}, {%0,%1,%2,%3};"
        : "+f"(acc[0]), "+f"(acc[1]), "+f"(acc[2]), "+f"(acc[3])
        : "r"(a[0]), "r"(a[1]), "r"(a[2]), "r"(a[3]), "r"(b0), "r"(b1));
}
__device__ __forceinline__ void cp_async16(uint32_t saddr, const void* gaddr) {
    asm volatile("cp.async.cg.shared.global [%0], [%1], 16;" :: "r"(saddr), "l"(gaddr));
}
#define CP_COMMIT() asm volatile("cp.async.commit_group;" ::: "memory")
#define CP_WAIT(n)  asm volatile("cp.async.wait_group %0;" :: "n"(n) : "memory")

__device__ __forceinline__ uint32_t pack_h2(float lo, float hi) {
    __half2 v = __floats2half2_rn(lo, hi);
    return *reinterpret_cast<uint32_t*>(&v);
}
__device__ __forceinline__ float ex2f(float x) {
    float y;
    asm("ex2.approx.f32 %0, %1;" : "=f"(y) : "f"(x));
    return y;
}

// ---------------------------------------------------------------------------
// gemm1: single-term fp16 GEMM, BK=64, 2-stage cp.async, race-safe ordering.
// A[M,K], B[N,K] fp16. CTA tile 128x128, 128 threads (4 warps), warp 64x64.
// __launch_bounds__(128, 3): 3 CTAs/SM.
// mode 0: plain fp32 out stride N.
// mode 1: fused QKV epilogue with in-register RoPE; Q additionally scaled by QSCALE.
// ---------------------------------------------------------------------------
#define ROWB   144
#define REGB   (128 * ROWB)          // 18432 per region (128 rows x 64 halves)
#define G1_STG (2 * REGB)            // A + B = 36864
#define G1_SMEM (2 * G1_STG)         // 73728 (double buffered)

__device__ __forceinline__ void g1_issue(uint32_t sbuf, const __half* a, const __half* b,
                                         int K, int tid) {
    const __half* srcs[2] = {a, b};
#pragma unroll
    for (int reg = 0; reg < 2; ++reg) {
        const __half* s = srcs[reg];
        uint32_t sr = sbuf + reg * REGB;
#pragma unroll
        for (int j = 0; j < 8; ++j) {
            int c = tid + j * 128;          // 0..1023
            int row = c >> 3, part = c & 7;
            cp_async16(sr + row * ROWB + part * 16, s + (size_t)row * K + part * 8);
        }
    }
}

__global__ __launch_bounds__(128, 3)
void gemm1_kernel(float* __restrict__ C,
                  __half* __restrict__ Oq, __half* __restrict__ Ok, __half* __restrict__ Ov,
                  const float2* __restrict__ tab,
                  const __half* __restrict__ A, const __half* __restrict__ B,
                  int M, int N, int K, int mode) {
    extern __shared__ char smem[];
    const uint32_t sbase = smem_u32(smem);
    const int tid = threadIdx.x;
    const int wid = tid >> 5, lane = tid & 31;
    const int warp_m = wid >> 1;          // 0..1 -> 64-row slab
    const int warp_n = wid & 1;           // 0..1 -> 64-col slab
    const int bm = blockIdx.y * 128, bn = blockIdx.x * 128;

    const __half* pA = A + (size_t)bm * K;
    const __half* pB = B + (size_t)bn * K;

    float acc[4][8][4];
#pragma unroll
    for (int i = 0; i < 4; ++i)
#pragma unroll
        for (int j = 0; j < 8; ++j)
#pragma unroll
            for (int k = 0; k < 4; ++k) acc[i][j][k] = 0.0f;

    const int NIT = K / 64;               // 32

    const uint32_t a_row = warp_m * 64 + (lane & 15);
    const uint32_t a_coff = (lane >> 4) * 16;
    const uint32_t b_rowbase = warp_n * 64 + (lane & 15);
    const uint32_t b_coff = (lane >> 4) * 16;

    g1_issue(sbase, pA, pB, K, tid);
    CP_COMMIT();

    int buf = 0;
    for (int it = 0; it < NIT; ++it) {
        CP_WAIT(0);                      // current stage resident
        __syncthreads();                 // everyone done with the other buffer
        if (it + 1 < NIT) {
            g1_issue(sbase + (buf ^ 1) * G1_STG,
                     pA + (it + 1) * 64, pB + (it + 1) * 64, K, tid);
            CP_COMMIT();
        }

        const uint32_t sbuf = sbase + buf * G1_STG;
        const uint32_t sA = sbuf, sB = sbuf + REGB;
#pragma unroll
        for (int ks = 0; ks < 4; ++ks) {
            const uint32_t kb = ks * 32;
            uint32_t bf[16];
#pragma unroll
            for (int p = 0; p < 4; ++p) {
                uint32_t ba = (b_rowbase + p * 16) * ROWB + kb + b_coff;
                ldmx4(&bf[p * 4], sB + ba);
            }
            uint32_t af[4][4];
#pragma unroll
            for (int mi = 0; mi < 4; ++mi) {
                uint32_t aa = (a_row + mi * 16) * ROWB + kb + a_coff;
                ldmx4(af[mi], sA + aa);
            }
#pragma unroll
            for (int mi = 0; mi < 4; ++mi)
#pragma unroll
                for (int ni = 0; ni < 8; ++ni) {
                    const int p = ni >> 1, q = ni & 1;
                    mma_f16(acc[mi][ni], af[mi], bf[p * 4 + q], bf[p * 4 + q + 2]);
                }
        }
        buf ^= 1;
    }

    const int rbase = bm + warp_m * 64 + (lane >> 2);
    const int j0 = (lane & 3) * 2;             // col-in-head base, < 8
    const int ch = bn + warp_n * 64;           // warp's global col base (one head)

    if (mode == 0) {
        const int cbase = ch + j0;
#pragma unroll
        for (int mi = 0; mi < 4; ++mi)
#pragma unroll
            for (int ni = 0; ni < 8; ++ni) {
                float* c0 = C + (size_t)(rbase + mi * 16) * N + cbase + ni * 8;
                float* c1 = C + (size_t)(rbase + mi * 16 + 8) * N + cbase + ni * 8;
                *(float2*)c0 = make_float2(acc[mi][ni][0], acc[mi][ni][1]);
                *(float2*)c1 = make_float2(acc[mi][ni][2], acc[mi][ni][3]);
            }
        return;
    }

    if (ch < 2560) {
        // Q or K: apply RoPE in-register, store fp16. Q also scaled by QSCALE.
        __half* dst;
        int ldc, cofs;
        float sc;
        if (ch < 2048) { dst = Oq; ldc = H_ * D_;  cofs = ch;        sc = QSCALE; }
        else           { dst = Ok; ldc = HKV_ * D_; cofs = ch - 2048; sc = 1.0f; }
#pragma unroll
        for (int mi = 0; mi < 4; ++mi) {
#pragma unroll
            for (int hf = 0; hf < 2; ++hf) {
                const int r = rbase + mi * 16 + hf * 8;
                const int t = r & (T_ - 1);
                const float2* trow = tab + t * 32;
#pragma unroll
                for (int ni0 = 0; ni0 < 4; ++ni0) {
                    const int j = j0 + ni0 * 8;          // < 32
                    float a1 = acc[mi][ni0][2 * hf + 0];
                    float a2 = acc[mi][ni0][2 * hf + 1];
                    float b1 = acc[mi][ni0 + 4][2 * hf + 0];
                    float b2 = acc[mi][ni0 + 4][2 * hf + 1];
                    float2 cs1 = trow[j];
                    float2 cs2 = trow[j + 1];
                    float o1 = (a1 * cs1.x - b1 * cs1.y) * sc;
                    float p1 = (b1 * cs1.x + a1 * cs1.y) * sc;
                    float o2 = (a2 * cs2.x - b2 * cs2.y) * sc;
                    float p2 = (b2 * cs2.x + a2 * cs2.y) * sc;
                    size_t base = (size_t)r * ldc + cofs + j;
                    *(uint32_t*)&dst[base]      = pack_h2(o1, o2);
                    *(uint32_t*)&dst[base + 32] = pack_h2(p1, p2);
                }
            }
        }
    } else {
        // V: plain fp16 store
        const int cbase = ch - 2560 + j0;
#pragma unroll
        for (int mi = 0; mi < 4; ++mi)
#pragma unroll
            for (int ni = 0; ni < 8; ++ni) {
                *(uint32_t*)&Ov[(size_t)(rbase + mi * 16) * 512 + cbase + ni * 8] =
                    pack_h2(acc[mi][ni][0], acc[mi][ni][1]);
                *(uint32_t*)&Ov[(size_t)(rbase + mi * 16 + 8) * 512 + cbase + ni * 8] =
                    pack_h2(acc[mi][ni][2], acc[mi][ni][3]);
            }
    }
}

// ---------------------------------------------------------------------------
// prep: x fp32 -> fp16 (vectorized) AND rope table, one launch
// ---------------------------------------------------------------------------
__global__ __launch_bounds__(256)
void prep_kernel(const float* __restrict__ in, __half* __restrict__ out,
                 float2* __restrict__ tab, int n4) {
    int i = blockIdx.x * blockDim.x + threadIdx.x;
    if (i < n4) {
        float4 v = ((const float4*)in)[i];
        ((uint2*)out)[i] = make_uint2(pack_h2(v.x, v.y), pack_h2(v.z, v.w));
    } else {
        int idx = i - n4;
        if (idx < T_ * 32) {
            int k = idx & 31, t = idx >> 5;
            float inv_freq = expf(-(float)k * (9.210340371976184f / 32.0f));
            float ang = (float)t * inv_freq;
            tab[idx] = make_float2(cosf(ang), sinf(ang));
        }
    }
}

// ---------------------------------------------------------------------------
// Vectorized transpose W[K,N] fp32 -> Tf[N,K] fp16, h2-packed stores.
// ---------------------------------------------------------------------------
__global__ __launch_bounds__(256)
void txpose_kernel(const float* __restrict__ W, __half* __restrict__ Tf,
                   int K, int N, int nofs) {
    __shared__ float t[64][33];
    const int tx = threadIdx.x, ty = threadIdx.y;
    const int n0 = blockIdx.x * 32, k0 = blockIdx.y * 64;
#pragma unroll
    for (int i = 0; i < 8; ++i)
        t[ty + i * 8][tx] = W[(size_t)(k0 + ty + i * 8) * N + n0 + tx];
    __syncthreads();
#pragma unroll
    for (int i = 0; i < 4; ++i) {
        int n = ty + i * 8;
        uint32_t v = pack_h2(t[2 * tx][n], t[2 * tx + 1][n]);
        *(uint32_t*)&Tf[(size_t)(nofs + n0 + n) * K + k0 + 2 * tx] = v;
    }
}

__global__ __launch_bounds__(256)
void txpose3_kernel(const float* __restrict__ Wq, const float* __restrict__ Wk,
                    const float* __restrict__ Wv, __half* __restrict__ Tf) {
    __shared__ float t[64][33];
    const int z = blockIdx.z;
    const float* W = (z == 0) ? Wq : (z == 1) ? Wk : Wv;
    const int N = (z == 0) ? (H_ * D_) : (HKV_ * D_);
    const int nofs = (z == 0) ? 0 : (z == 1) ? 2048 : 2560;
    const int n0 = blockIdx.x * 32, k0 = blockIdx.y * 64;
    if (n0 >= N) return;
    const int tx = threadIdx.x, ty = threadIdx.y;
#pragma unroll
    for (int i = 0; i < 8; ++i)
        t[ty + i * 8][tx] = W[(size_t)(k0 + ty + i * 8) * N + n0 + tx];
    __syncthreads();
#pragma unroll
    for (int i = 0; i < 4; ++i) {
        int n = ty + i * 8;
        uint32_t v = pack_h2(t[2 * tx][n], t[2 * tx + 1][n]);
        *(uint32_t*)&Tf[(size_t)(nofs + n0 + n) * E_ + k0 + 2 * tx] = v;
    }
}

// ---------------------------------------------------------------------------
// FA2-style causal attention, fp16 mma.sync. Q pre-scaled by scale*log2e;
// softmax uses ex2 directly. Race-safe KV pipeline, reversed tile order.
// ---------------------------------------------------------------------------
#define AROWB 144
#define KVREG (64 * AROWB)              // 9216
#define KVBUF (2 * KVREG)               // 18432
#define QREG  (128 * AROWB)             // 18432
#define ATT_SMEM (QREG + 2 * KVBUF)     // 55296

__global__ __launch_bounds__(256)
void attn_f16_kernel(__half* __restrict__ Yf,
                     const __half* __restrict__ Qf, const __half* __restrict__ Kf,
                     const __half* __restrict__ Vf) {
    extern __shared__ char smem[];
    const uint32_t sbase = smem_u32(smem);
    const uint32_t sQ = sbase;
    const uint32_t sKV = sbase + QREG;

    const int tid = threadIdx.x;
    const int wid = tid >> 5, lane = tid & 31;
    const int qb = gridDim.x - 1 - blockIdx.x;    // reversed: big tiles first
    const int h  = blockIdx.y;
    const int b  = blockIdx.z;
    const int kh = h >> 2;
    const int bT0 = b * T_;

    const int row0 = qb * 128 + wid * 16 + (lane >> 2);
    const int row1 = row0 + 8;
    const int rowmin_w = qb * 128 + wid * 16;
    const int rowmax_w = rowmin_w + 15;

#pragma unroll
    for (int j = 0; j < 4; ++j) {
        int c = tid + j * 256;
        int row = c >> 3, part = c & 7;
        cp_async16(sQ + row * AROWB + part * 16,
                   Qf + (size_t)(bT0 + qb * 128 + row) * (H_ * D_) + h * 64 + part * 8);
    }
#pragma unroll
    for (int j = 0; j < 4; ++j) {
        int c = tid + j * 256;
        int reg = c >> 9, idx = c & 511;
        int row = idx >> 3, part = idx & 7;
        const __half* src = reg ? Vf : Kf;
        cp_async16(sKV + reg * KVREG + row * AROWB + part * 16,
                   src + (size_t)(bT0 + row) * (HKV_ * D_) + kh * 64 + part * 8);
    }
    CP_COMMIT();
    CP_WAIT(0);
    __syncthreads();

    uint32_t qf[4][4];
#pragma unroll
    for (int ks = 0; ks < 4; ++ks) {
        uint32_t qa = (wid * 16 + (lane & 15)) * AROWB + ks * 32 + (lane >> 4) * 16;
        ldmx4(qf[ks], sQ + qa);
    }

    float o[8][4];
#pragma unroll
    for (int j = 0; j < 8; ++j)
#pragma unroll
        for (int k = 0; k < 4; ++k) o[j][k] = 0.0f;
    float m0 = -1e30f, m1 = -1e30f, l0 = 0.0f, l1 = 0.0f;

    const int NT = 2 * qb + 2;
    int buf = 0;
    for (int it = 0; it < NT; ++it) {
        CP_WAIT(0);                      // tile `it` resident
        __syncthreads();                 // everyone done with the other buffer
        if (it + 1 < NT) {
            uint32_t sb = sKV + (buf ^ 1) * KVBUF;
#pragma unroll
            for (int j = 0; j < 4; ++j) {
                int c = tid + j * 256;
                int reg = c >> 9, idx = c & 511;
                int row = idx >> 3, part = idx & 7;
                const __half* src = reg ? Vf : Kf;
                cp_async16(sb + reg * KVREG + row * AROWB + part * 16,
                           src + (size_t)(bT0 + (it + 1) * 64 + row) * (HKV_ * D_) + kh * 64 + part * 8);
            }
            CP_COMMIT();
        }

        const int kt = it;
        if (kt * 64 <= rowmax_w) {
            const uint32_t sb = sKV + buf * KVBUF;
            const uint32_t sK = sb, sV = sb + KVREG;

            float s[8][4];
#pragma unroll
            for (int j = 0; j < 8; ++j)
#pragma unroll
                for (int k = 0; k < 4; ++k) s[j][k] = 0.0f;

#pragma unroll
            for (int ks = 0; ks < 4; ++ks) {
#pragma unroll
                for (int pg = 0; pg < 2; ++pg) {
                    uint32_t kf[2][4];
#pragma unroll
                    for (int pp = 0; pp < 2; ++pp) {
                        uint32_t ka = ((2 * pg + pp) * 16 + (lane & 15)) * AROWB + ks * 32 + (lane >> 4) * 16;
                        ldmx4(kf[pp], sK + ka);
                    }
#pragma unroll
                    for (int pp = 0; pp < 2; ++pp)
#pragma unroll
                        for (int q = 0; q < 2; ++q)
                            mma_f16(s[(2 * pg + pp) * 2 + q], qf[ks], kf[pp][q], kf[pp][q + 2]);
                }
            }

            // logits are already in log2-scaled space (Q pre-scaled)
            const bool needs_mask = (kt * 64 + 63) > rowmin_w;
            if (needs_mask) {
#pragma unroll
                for (int j = 0; j < 8; ++j) {
                    int colb = kt * 64 + j * 8 + 2 * (lane & 3);
                    if (colb > row0)     s[j][0] = -1e30f;
                    if (colb + 1 > row0) s[j][1] = -1e30f;
                    if (colb > row1)     s[j][2] = -1e30f;
                    if (colb + 1 > row1) s[j][3] = -1e30f;
                }
            }

            float mx0 = -1e30f, mx1 = -1e30f;
#pragma unroll
            for (int j = 0; j < 8; ++j) {
                mx0 = fmaxf(mx0, fmaxf(s[j][0], s[j][1]));
                mx1 = fmaxf(mx1, fmaxf(s[j][2], s[j][3]));
            }
            mx0 = fmaxf(mx0, __shfl_xor_sync(0xFFFFFFFF, mx0, 1));
            mx0 = fmaxf(mx0, __shfl_xor_sync(0xFFFFFFFF, mx0, 2));
            mx1 = fmaxf(mx1, __shfl_xor_sync(0xFFFFFFFF, mx1, 1));
            mx1 = fmaxf(mx1, __shfl_xor_sync(0xFFFFFFFF, mx1, 2));

            float mn0 = fmaxf(m0, mx0), mn1 = fmaxf(m1, mx1);
            float c0 = ex2f(m0 - mn0), c1 = ex2f(m1 - mn1);
            m0 = mn0; m1 = mn1;
            l0 *= c0; l1 *= c1;
#pragma unroll
            for (int j = 0; j < 8; ++j) {
                o[j][0] *= c0; o[j][1] *= c0; o[j][2] *= c1; o[j][3] *= c1;
            }
#pragma unroll
            for (int j = 0; j < 8; ++j) {
                s[j][0] = ex2f(s[j][0] - mn0);
                s[j][1] = ex2f(s[j][1] - mn0);
                s[j][2] = ex2f(s[j][2] - mn1);
                s[j][3] = ex2f(s[j][3] - mn1);
                l0 += s[j][0] + s[j][1];
                l1 += s[j][2] + s[j][3];
            }

#pragma unroll
            for (int ks = 0; ks < 4; ++ks) {
                uint32_t pa[4];
                pa[0] = pack_h2(s[2 * ks][0], s[2 * ks][1]);
                pa[1] = pack_h2(s[2 * ks][2], s[2 * ks][3]);
                pa[2] = pack_h2(s[2 * ks + 1][0], s[2 * ks + 1][1]);
                pa[3] = pack_h2(s[2 * ks + 1][2], s[2 * ks + 1][3]);
#pragma unroll
                for (int pg = 0; pg < 2; ++pg) {
                    uint32_t vf[2][4];
#pragma unroll
                    for (int pp = 0; pp < 2; ++pp) {
                        uint32_t va = (ks * 16 + (lane & 15)) * AROWB + (2 * pg + pp) * 32 + (lane >> 4) * 16;
                        ldmx4t(vf[pp], sV + va);
                    }
#pragma unroll
                    for (int pp = 0; pp < 2; ++pp)
#pragma unroll
                        for (int q = 0; q < 2; ++q)
                            mma_f16(o[(2 * pg + pp) * 2 + q], pa, vf[pp][2 * q], vf[pp][2 * q + 1]);
                }
            }
        }
        buf ^= 1;
    }

    l0 += __shfl_xor_sync(0xFFFFFFFF, l0, 1);
    l0 += __shfl_xor_sync(0xFFFFFFFF, l0, 2);
    l1 += __shfl_xor_sync(0xFFFFFFFF, l1, 1);
    l1 += __shfl_xor_sync(0xFFFFFFFF, l1, 2);
    float inv0 = 1.0f / l0, inv1 = 1.0f / l1;

#pragma unroll
    for (int j = 0; j < 8; ++j) {
        int col = j * 8 + 2 * (lane & 3);
        size_t a0 = ((size_t)(bT0 + row0) * H_ + h) * 64 + col;
        size_t a1 = ((size_t)(bT0 + row1) * H_ + h) * 64 + col;
        *(uint32_t*)&Yf[a0] = pack_h2(o[j][0] * inv0, o[j][1] * inv0);
        *(uint32_t*)&Yf[a1] = pack_h2(o[j][2] * inv1, o[j][3] * inv1);
    }
}

// ---------------------------------------------------------------------------
// kernel_launch — attention is our 4th launch (ncu capture target)
// ---------------------------------------------------------------------------
extern "C" void kernel_launch(void* const* d_in, const int* in_sizes, int n_in,
                              void* d_out, int out_size) {
    const float* x  = (const float*)d_in[0];
    const float* Wq = (const float*)d_in[1];
    const float* Wk = (const float*)d_in[2];
    const float* Wv = (const float*)d_in[3];
    const float* Wo = (const float*)d_in[4];
    float* out = (float*)d_out;

    __half *pxf, *pQf, *pKf, *pVf, *pYf, *pWcf, *pWof;
    float2* ptab;
    cudaGetSymbolAddress((void**)&pxf, g_xf);
    cudaGetSymbolAddress((void**)&pQf, g_Qf);
    cudaGetSymbolAddress((void**)&pKf, g_Kf);
    cudaGetSymbolAddress((void**)&pVf, g_Vf);
    cudaGetSymbolAddress((void**)&pYf, g_Yf);
    cudaGetSymbolAddress((void**)&pWcf, g_Wcf);
    cudaGetSymbolAddress((void**)&pWof, g_Wof);
    cudaGetSymbolAddress((void**)&ptab, g_tab);

    cudaFuncSetAttribute(gemm1_kernel, cudaFuncAttributeMaxDynamicSharedMemorySize, G1_SMEM);
    cudaFuncSetAttribute(attn_f16_kernel, cudaFuncAttributeMaxDynamicSharedMemorySize, ATT_SMEM);

    // #1 x -> fp16 + rope table (fused)
    {
        int n4 = (BT_ * E_) / 4;
        int total = n4 + T_ * 32;
        prep_kernel<<<(total + 255) / 256, 256>>>(x, pxf, ptab, n4);
    }
    // #2 fused transpose Wq|Wk|Wv -> fp16 concat
    txpose3_kernel<<<dim3(64, 32, 3), dim3(32, 8)>>>(Wq, Wk, Wv, pWcf);

    // #3 fused QKV projection with in-epilogue RoPE (+ Q pre-scale)
    gemm1_kernel<<<dim3(NQKV / 128, BT_ / 128), 128, G1_SMEM>>>(
        nullptr, pQf, pKf, pVf, ptab, pxf, pWcf, BT_, NQKV, E_, 1);

    // #4 attention (ncu capture target)
    attn_f16_kernel<<<dim3(T_ / 128, H_, B_), 256, ATT_SMEM>>>(pYf, pQf, pKf, pVf);

    // #5 transpose Wo -> fp16
    txpose_kernel<<<dim3(64, 32), dim3(32, 8)>>>(Wo, pWof, E_, E_, 0);

    // #6 output projection, single-term fp16
    gemm1_kernel<<<dim3(E_ / 128, BT_ / 128), 128, G1_SMEM>>>(
        out, nullptr, nullptr, nullptr, nullptr, pYf, pWof, BT_, E_, E_, 0);
}

// round 14
// speedup vs baseline: 1.0431x; 1.0431x over previous
#include <cuda_runtime.h>
#include <cuda_bf16.h>
#include <cuda_fp16.h>
#include <cstdint>
#include <math.h>

// Problem constants
#define B_  2
#define T_  2048
#define E_  2048
#define H_  32
#define HKV_ 8
#define D_  64
#define BT_ (B_*T_)  // 4096
#define NQKV 3072    // 2048 Q + 512 K + 512 V

// scale * log2(e): folded into Q at projection time; attention uses ex2 directly
#define QSCALE 0.1803368801111357f   // 0.125 * 1.4426950408889634

// ---------------------------------------------------------------------------
// Scratch (static device globals — allocation-free rule)
// ---------------------------------------------------------------------------
__device__ __half g_xf[BT_ * E_];               // x in fp16
__device__ __half g_Qf[BT_ * H_ * D_];          // post-rope, pre-scaled Q fp16
__device__ __half g_Kf[BT_ * HKV_ * D_];        // post-rope K fp16
__device__ __half g_Vf[BT_ * HKV_ * D_];
__device__ __half g_Yf[BT_ * E_];               // attention output fp16
__device__ __half g_Wcf[NQKV * E_];             // concat Wq|Wk|Wv transposed [N,K] fp16
__device__ __half g_Wof[E_ * E_];               // Wo transposed fp16
__device__ float2 g_tab[T_ * 32];               // rope cos/sin table

// ---------------------------------------------------------------------------
// PTX helpers
// ---------------------------------------------------------------------------
__device__ __forceinline__ uint32_t smem_u32(const void* p) {
    uint32_t a;
    asm("{ .reg .u64 t; cvta.to.shared.u64 t, %1; cvt.u32.u64 %0, t; }" : "=r"(a) : "l"(p));
    return a;
}
__device__ __forceinline__ void ldmx4(uint32_t* r, uint32_t addr) {
    asm volatile("ldmatrix.sync.aligned.m8n8.x4.shared.b16 {%0,%1,%2,%3}, [%4];"
                 : "=r"(r[0]), "=r"(r[1]), "=r"(r[2]), "=r"(r[3]) : "r"(addr));
}
__device__ __forceinline__ void ldmx4t(uint32_t* r, uint32_t addr) {
    asm volatile("ldmatrix.sync.aligned.m8n8.x4.trans.shared.b16 {%0,%1,%2,%3}, [%4];"
                 : "=r"(r[0]), "=r"(r[1]), "=r"(r[2]), "=r"(r[3]) : "r"(addr));
}
__device__ __forceinline__ void mma_f16(float* acc, const uint32_t* a, const uint32_t b0,
                                        const uint32_t b1) {
    asm volatile(
        "mma.sync.aligned.m16n8k16.row.col.f32.f16.f16.f32 "
        "{%0,%1,%2,%3}, {%4,%5,%6,%7}, {%8,%9}, {%0,%1,%2,%3};"
        : "+f"(acc[0]), "+f"(acc[1]), "+f"(acc[2]), "+f"(acc[3])
        : "r"(a[0]), "r"(a[1]), "r"(a[2]), "r"(a[3]), "r"(b0), "r"(b1));
}
__device__ __forceinline__ void cp_async16(uint32_t saddr, const void* gaddr) {
    asm volatile("cp.async.cg.shared.global [%0], [%1], 16;" :: "r"(saddr), "l"(gaddr));
}
#define CP_COMMIT() asm volatile("cp.async.commit_group;" ::: "memory")
#define CP_WAIT(n)  asm volatile("cp.async.wait_group %0;" :: "n"(n) : "memory")

__device__ __forceinline__ uint32_t pack_h2(float lo, float hi) {
    __half2 v = __floats2half2_rn(lo, hi);
    return *reinterpret_cast<uint32_t*>(&v);
}
__device__ __forceinline__ float ex2f(float x) {
    float y;
    asm("ex2.approx.f32 %0, %1;" : "=f"(y) : "f"(x));
    return y;
}

// ---------------------------------------------------------------------------
// gemm1: single-term fp16 GEMM, BK=64, 2-stage cp.async, race-safe ordering.
// A[M,K], B[N,K] fp16. CTA tile 128x128, 128 threads (4 warps), warp 64x64.
// __launch_bounds__(128, 3): 3 CTAs/SM.
// mode 0: plain fp32 out stride N.
// mode 1: fused QKV epilogue with in-register RoPE; Q additionally scaled by QSCALE.
// ---------------------------------------------------------------------------
#define ROWB   144
#define REGB   (128 * ROWB)          // 18432 per region (128 rows x 64 halves)
#define G1_STG (2 * REGB)            // A + B = 36864
#define G1_SMEM (2 * G1_STG)         // 73728 (double buffered)

__device__ __forceinline__ void g1_issue(uint32_t sbuf, const __half* a, const __half* b,
                                         int K, int tid) {
    const __half* srcs[2] = {a, b};
#pragma unroll
    for (int reg = 0; reg < 2; ++reg) {
        const __half* s = srcs[reg];
        uint32_t sr = sbuf + reg * REGB;
#pragma unroll
        for (int j = 0; j < 8; ++j) {
            int c = tid + j * 128;          // 0..1023
            int row = c >> 3, part = c & 7;
            cp_async16(sr + row * ROWB + part * 16, s + (size_t)row * K + part * 8);
        }
    }
}

__global__ __launch_bounds__(128, 3)
void gemm1_kernel(float* __restrict__ C,
                  __half* __restrict__ Oq, __half* __restrict__ Ok, __half* __restrict__ Ov,
                  const float2* __restrict__ tab,
                  const __half* __restrict__ A, const __half* __restrict__ B,
                  int M, int N, int K, int mode) {
    extern __shared__ char smem[];
    const uint32_t sbase = smem_u32(smem);
    const int tid = threadIdx.x;
    const int wid = tid >> 5, lane = tid & 31;
    const int warp_m = wid >> 1;          // 0..1 -> 64-row slab
    const int warp_n = wid & 1;           // 0..1 -> 64-col slab
    const int bm = blockIdx.y * 128, bn = blockIdx.x * 128;

    const __half* pA = A + (size_t)bm * K;
    const __half* pB = B + (size_t)bn * K;

    float acc[4][8][4];
#pragma unroll
    for (int i = 0; i < 4; ++i)
#pragma unroll
        for (int j = 0; j < 8; ++j)
#pragma unroll
            for (int k = 0; k < 4; ++k) acc[i][j][k] = 0.0f;

    const int NIT = K / 64;               // 32

    const uint32_t a_row = warp_m * 64 + (lane & 15);
    const uint32_t a_coff = (lane >> 4) * 16;
    const uint32_t b_rowbase = warp_n * 64 + (lane & 15);
    const uint32_t b_coff = (lane >> 4) * 16;

    g1_issue(sbase, pA, pB, K, tid);
    CP_COMMIT();

    int buf = 0;
    for (int it = 0; it < NIT; ++it) {
        CP_WAIT(0);                      // current stage resident
        __syncthreads();                 // everyone done with the other buffer
        if (it + 1 < NIT) {
            g1_issue(sbase + (buf ^ 1) * G1_STG,
                     pA + (it + 1) * 64, pB + (it + 1) * 64, K, tid);
            CP_COMMIT();
        }

        const uint32_t sbuf = sbase + buf * G1_STG;
        const uint32_t sA = sbuf, sB = sbuf + REGB;
#pragma unroll
        for (int ks = 0; ks < 4; ++ks) {
            const uint32_t kb = ks * 32;
            uint32_t bf[16];
#pragma unroll
            for (int p = 0; p < 4; ++p) {
                uint32_t ba = (b_rowbase + p * 16) * ROWB + kb + b_coff;
                ldmx4(&bf[p * 4], sB + ba);
            }
            uint32_t af[4][4];
#pragma unroll
            for (int mi = 0; mi < 4; ++mi) {
                uint32_t aa = (a_row + mi * 16) * ROWB + kb + a_coff;
                ldmx4(af[mi], sA + aa);
            }
#pragma unroll
            for (int mi = 0; mi < 4; ++mi)
#pragma unroll
                for (int ni = 0; ni < 8; ++ni) {
                    const int p = ni >> 1, q = ni & 1;
                    mma_f16(acc[mi][ni], af[mi], bf[p * 4 + q], bf[p * 4 + q + 2]);
                }
        }
        buf ^= 1;
    }

    const int rbase = bm + warp_m * 64 + (lane >> 2);
    const int j0 = (lane & 3) * 2;             // col-in-head base, < 8
    const int ch = bn + warp_n * 64;           // warp's global col base (one head)

    if (mode == 0) {
        const int cbase = ch + j0;
#pragma unroll
        for (int mi = 0; mi < 4; ++mi)
#pragma unroll
            for (int ni = 0; ni < 8; ++ni) {
                float* c0 = C + (size_t)(rbase + mi * 16) * N + cbase + ni * 8;
                float* c1 = C + (size_t)(rbase + mi * 16 + 8) * N + cbase + ni * 8;
                *(float2*)c0 = make_float2(acc[mi][ni][0], acc[mi][ni][1]);
                *(float2*)c1 = make_float2(acc[mi][ni][2], acc[mi][ni][3]);
            }
        return;
    }

    if (ch < 2560) {
        // Q or K: apply RoPE in-register, store fp16. Q also scaled by QSCALE.
        __half* dst;
        int ldc, cofs;
        float sc;
        if (ch < 2048) { dst = Oq; ldc = H_ * D_;  cofs = ch;        sc = QSCALE; }
        else           { dst = Ok; ldc = HKV_ * D_; cofs = ch - 2048; sc = 1.0f; }
#pragma unroll
        for (int mi = 0; mi < 4; ++mi) {
#pragma unroll
            for (int hf = 0; hf < 2; ++hf) {
                const int r = rbase + mi * 16 + hf * 8;
                const int t = r & (T_ - 1);
                const float2* trow = tab + t * 32;
#pragma unroll
                for (int ni0 = 0; ni0 < 4; ++ni0) {
                    const int j = j0 + ni0 * 8;          // < 32
                    float a1 = acc[mi][ni0][2 * hf + 0];
                    float a2 = acc[mi][ni0][2 * hf + 1];
                    float b1 = acc[mi][ni0 + 4][2 * hf + 0];
                    float b2 = acc[mi][ni0 + 4][2 * hf + 1];
                    float2 cs1 = trow[j];
                    float2 cs2 = trow[j + 1];
                    float o1 = (a1 * cs1.x - b1 * cs1.y) * sc;
                    float p1 = (b1 * cs1.x + a1 * cs1.y) * sc;
                    float o2 = (a2 * cs2.x - b2 * cs2.y) * sc;
                    float p2 = (b2 * cs2.x + a2 * cs2.y) * sc;
                    size_t base = (size_t)r * ldc + cofs + j;
                    *(uint32_t*)&dst[base]      = pack_h2(o1, o2);
                    *(uint32_t*)&dst[base + 32] = pack_h2(p1, p2);
                }
            }
        }
    } else {
        // V: plain fp16 store
        const int cbase = ch - 2560 + j0;
#pragma unroll
        for (int mi = 0; mi < 4; ++mi)
#pragma unroll
            for (int ni = 0; ni < 8; ++ni) {
                *(uint32_t*)&Ov[(size_t)(rbase + mi * 16) * 512 + cbase + ni * 8] =
                    pack_h2(acc[mi][ni][0], acc[mi][ni][1]);
                *(uint32_t*)&Ov[(size_t)(rbase + mi * 16 + 8) * 512 + cbase + ni * 8] =
                    pack_h2(acc[mi][ni][2], acc[mi][ni][3]);
            }
    }
}

// ---------------------------------------------------------------------------
// prep: x fp32 -> fp16 (vectorized) AND rope table, one launch
// ---------------------------------------------------------------------------
__global__ __launch_bounds__(256)
void prep_kernel(const float* __restrict__ in, __half* __restrict__ out,
                 float2* __restrict__ tab, int n4) {
    int i = blockIdx.x * blockDim.x + threadIdx.x;
    if (i < n4) {
        float4 v = ((const float4*)in)[i];
        ((uint2*)out)[i] = make_uint2(pack_h2(v.x, v.y), pack_h2(v.z, v.w));
    } else {
        int idx = i - n4;
        if (idx < T_ * 32) {
            int k = idx & 31, t = idx >> 5;
            float inv_freq = expf(-(float)k * (9.210340371976184f / 32.0f));
            float ang = (float)t * inv_freq;
            tab[idx] = make_float2(cosf(ang), sinf(ang));
        }
    }
}

// ---------------------------------------------------------------------------
// Vectorized transpose W[K,N] fp32 -> Tf[N,K] fp16, h2-packed stores.
// ---------------------------------------------------------------------------
__global__ __launch_bounds__(256)
void txpose_kernel(const float* __restrict__ W, __half* __restrict__ Tf,
                   int K, int N, int nofs) {
    __shared__ float t[64][33];
    const int tx = threadIdx.x, ty = threadIdx.y;
    const int n0 = blockIdx.x * 32, k0 = blockIdx.y * 64;
#pragma unroll
    for (int i = 0; i < 8; ++i)
        t[ty + i * 8][tx] = W[(size_t)(k0 + ty + i * 8) * N + n0 + tx];
    __syncthreads();
#pragma unroll
    for (int i = 0; i < 4; ++i) {
        int n = ty + i * 8;
        uint32_t v = pack_h2(t[2 * tx][n], t[2 * tx + 1][n]);
        *(uint32_t*)&Tf[(size_t)(nofs + n0 + n) * K + k0 + 2 * tx] = v;
    }
}

__global__ __launch_bounds__(256)
void txpose3_kernel(const float* __restrict__ Wq, const float* __restrict__ Wk,
                    const float* __restrict__ Wv, __half* __restrict__ Tf) {
    __shared__ float t[64][33];
    const int z = blockIdx.z;
    const float* W = (z == 0) ? Wq : (z == 1) ? Wk : Wv;
    const int N = (z == 0) ? (H_ * D_) : (HKV_ * D_);
    const int nofs = (z == 0) ? 0 : (z == 1) ? 2048 : 2560;
    const int n0 = blockIdx.x * 32, k0 = blockIdx.y * 64;
    if (n0 >= N) return;
    const int tx = threadIdx.x, ty = threadIdx.y;
#pragma unroll
    for (int i = 0; i < 8; ++i)
        t[ty + i * 8][tx] = W[(size_t)(k0 + ty + i * 8) * N + n0 + tx];
    __syncthreads();
#pragma unroll
    for (int i = 0; i < 4; ++i) {
        int n = ty + i * 8;
        uint32_t v = pack_h2(t[2 * tx][n], t[2 * tx + 1][n]);
        *(uint32_t*)&Tf[(size_t)(nofs + n0 + n) * E_ + k0 + 2 * tx] = v;
    }
}

// ---------------------------------------------------------------------------
// FA2-style causal attention, fp16 mma.sync. Q pre-scaled by scale*log2e;
// softmax uses ex2 directly. Race-safe KV pipeline, reversed tile order.
// __launch_bounds__(256, 2): cap regs at 128 -> 2 CTAs/SM.
// ---------------------------------------------------------------------------
#define AROWB 144
#define KVREG (64 * AROWB)              // 9216
#define KVBUF (2 * KVREG)               // 18432
#define QREG  (128 * AROWB)             // 18432
#define ATT_SMEM (QREG + 2 * KVBUF)     // 55296

__global__ __launch_bounds__(256, 2)
void attn_f16_kernel(__half* __restrict__ Yf,
                     const __half* __restrict__ Qf, const __half* __restrict__ Kf,
                     const __half* __restrict__ Vf) {
    extern __shared__ char smem[];
    const uint32_t sbase = smem_u32(smem);
    const uint32_t sQ = sbase;
    const uint32_t sKV = sbase + QREG;

    const int tid = threadIdx.x;
    const int wid = tid >> 5, lane = tid & 31;
    const int qb = gridDim.x - 1 - blockIdx.x;    // reversed: big tiles first
    const int h  = blockIdx.y;
    const int b  = blockIdx.z;
    const int kh = h >> 2;
    const int bT0 = b * T_;

    const int row0 = qb * 128 + wid * 16 + (lane >> 2);
    const int row1 = row0 + 8;
    const int rowmin_w = qb * 128 + wid * 16;
    const int rowmax_w = rowmin_w + 15;

#pragma unroll
    for (int j = 0; j < 4; ++j) {
        int c = tid + j * 256;
        int row = c >> 3, part = c & 7;
        cp_async16(sQ + row * AROWB + part * 16,
                   Qf + (size_t)(bT0 + qb * 128 + row) * (H_ * D_) + h * 64 + part * 8);
    }
#pragma unroll
    for (int j = 0; j < 4; ++j) {
        int c = tid + j * 256;
        int reg = c >> 9, idx = c & 511;
        int row = idx >> 3, part = idx & 7;
        const __half* src = reg ? Vf : Kf;
        cp_async16(sKV + reg * KVREG + row * AROWB + part * 16,
                   src + (size_t)(bT0 + row) * (HKV_ * D_) + kh * 64 + part * 8);
    }
    CP_COMMIT();
    CP_WAIT(0);
    __syncthreads();

    uint32_t qf[4][4];
#pragma unroll
    for (int ks = 0; ks < 4; ++ks) {
        uint32_t qa = (wid * 16 + (lane & 15)) * AROWB + ks * 32 + (lane >> 4) * 16;
        ldmx4(qf[ks], sQ + qa);
    }

    float o[8][4];
#pragma unroll
    for (int j = 0; j < 8; ++j)
#pragma unroll
        for (int k = 0; k < 4; ++k) o[j][k] = 0.0f;
    float m0 = -1e30f, m1 = -1e30f, l0 = 0.0f, l1 = 0.0f;

    const int NT = 2 * qb + 2;
    int buf = 0;
    for (int it = 0; it < NT; ++it) {
        CP_WAIT(0);                      // tile `it` resident
        __syncthreads();                 // everyone done with the other buffer
        if (it + 1 < NT) {
            uint32_t sb = sKV + (buf ^ 1) * KVBUF;
#pragma unroll
            for (int j = 0; j < 4; ++j) {
                int c = tid + j * 256;
                int reg = c >> 9, idx = c & 511;
                int row = idx >> 3, part = idx & 7;
                const __half* src = reg ? Vf : Kf;
                cp_async16(sb + reg * KVREG + row * AROWB + part * 16,
                           src + (size_t)(bT0 + (it + 1) * 64 + row) * (HKV_ * D_) + kh * 64 + part * 8);
            }
            CP_COMMIT();
        }

        const int kt = it;
        if (kt * 64 <= rowmax_w) {
            const uint32_t sb = sKV + buf * KVBUF;
            const uint32_t sK = sb, sV = sb + KVREG;

            float s[8][4];
#pragma unroll
            for (int j = 0; j < 8; ++j)
#pragma unroll
                for (int k = 0; k < 4; ++k) s[j][k] = 0.0f;

#pragma unroll
            for (int ks = 0; ks < 4; ++ks) {
#pragma unroll
                for (int pg = 0; pg < 2; ++pg) {
                    uint32_t kf[2][4];
#pragma unroll
                    for (int pp = 0; pp < 2; ++pp) {
                        uint32_t ka = ((2 * pg + pp) * 16 + (lane & 15)) * AROWB + ks * 32 + (lane >> 4) * 16;
                        ldmx4(kf[pp], sK + ka);
                    }
#pragma unroll
                    for (int pp = 0; pp < 2; ++pp)
#pragma unroll
                        for (int q = 0; q < 2; ++q)
                            mma_f16(s[(2 * pg + pp) * 2 + q], qf[ks], kf[pp][q], kf[pp][q + 2]);
                }
            }

            // logits are already in log2-scaled space (Q pre-scaled)
            const bool needs_mask = (kt * 64 + 63) > rowmin_w;
            if (needs_mask) {
#pragma unroll
                for (int j = 0; j < 8; ++j) {
                    int colb = kt * 64 + j * 8 + 2 * (lane & 3);
                    if (colb > row0)     s[j][0] = -1e30f;
                    if (colb + 1 > row0) s[j][1] = -1e30f;
                    if (colb > row1)     s[j][2] = -1e30f;
                    if (colb + 1 > row1) s[j][3] = -1e30f;
                }
            }

            float mx0 = -1e30f, mx1 = -1e30f;
#pragma unroll
            for (int j = 0; j < 8; ++j) {
                mx0 = fmaxf(mx0, fmaxf(s[j][0], s[j][1]));
                mx1 = fmaxf(mx1, fmaxf(s[j][2], s[j][3]));
            }
            mx0 = fmaxf(mx0, __shfl_xor_sync(0xFFFFFFFF, mx0, 1));
            mx0 = fmaxf(mx0, __shfl_xor_sync(0xFFFFFFFF, mx0, 2));
            mx1 = fmaxf(mx1, __shfl_xor_sync(0xFFFFFFFF, mx1, 1));
            mx1 = fmaxf(mx1, __shfl_xor_sync(0xFFFFFFFF, mx1, 2));

            float mn0 = fmaxf(m0, mx0), mn1 = fmaxf(m1, mx1);
            float c0 = ex2f(m0 - mn0), c1 = ex2f(m1 - mn1);
            m0 = mn0; m1 = mn1;
            l0 *= c0; l1 *= c1;
#pragma unroll
            for (int j = 0; j < 8; ++j) {
                o[j][0] *= c0; o[j][1] *= c0; o[j][2] *= c1; o[j][3] *= c1;
            }
#pragma unroll
            for (int j = 0; j < 8; ++j) {
                s[j][0] = ex2f(s[j][0] - mn0);
                s[j][1] = ex2f(s[j][1] - mn0);
                s[j][2] = ex2f(s[j][2] - mn1);
                s[j][3] = ex2f(s[j][3] - mn1);
                l0 += s[j][0] + s[j][1];
                l1 += s[j][2] + s[j][3];
            }

#pragma unroll
            for (int ks = 0; ks < 4; ++ks) {
                uint32_t pa[4];
                pa[0] = pack_h2(s[2 * ks][0], s[2 * ks][1]);
                pa[1] = pack_h2(s[2 * ks][2], s[2 * ks][3]);
                pa[2] = pack_h2(s[2 * ks + 1][0], s[2 * ks + 1][1]);
                pa[3] = pack_h2(s[2 * ks + 1][2], s[2 * ks + 1][3]);
#pragma unroll
                for (int pg = 0; pg < 2; ++pg) {
                    uint32_t vf[2][4];
#pragma unroll
                    for (int pp = 0; pp < 2; ++pp) {
                        uint32_t va = (ks * 16 + (lane & 15)) * AROWB + (2 * pg + pp) * 32 + (lane >> 4) * 16;
                        ldmx4t(vf[pp], sV + va);
                    }
#pragma unroll
                    for (int pp = 0; pp < 2; ++pp)
#pragma unroll
                        for (int q = 0; q < 2; ++q)
                            mma_f16(o[(2 * pg + pp) * 2 + q], pa, vf[pp][2 * q], vf[pp][2 * q + 1]);
                }
            }
        }
        buf ^= 1;
    }

    l0 += __shfl_xor_sync(0xFFFFFFFF, l0, 1);
    l0 += __shfl_xor_sync(0xFFFFFFFF, l0, 2);
    l1 += __shfl_xor_sync(0xFFFFFFFF, l1, 1);
    l1 += __shfl_xor_sync(0xFFFFFFFF, l1, 2);
    float inv0 = 1.0f / l0, inv1 = 1.0f / l1;

#pragma unroll
    for (int j = 0; j < 8; ++j) {
        int col = j * 8 + 2 * (lane & 3);
        size_t a0 = ((size_t)(bT0 + row0) * H_ + h) * 64 + col;
        size_t a1 = ((size_t)(bT0 + row1) * H_ + h) * 64 + col;
        *(uint32_t*)&Yf[a0] = pack_h2(o[j][0] * inv0, o[j][1] * inv0);
        *(uint32_t*)&Yf[a1] = pack_h2(o[j][2] * inv1, o[j][3] * inv1);
    }
}

// ---------------------------------------------------------------------------
// kernel_launch — attention is our 4th launch (ncu capture target)
// ---------------------------------------------------------------------------
extern "C" void kernel_launch(void* const* d_in, const int* in_sizes, int n_in,
                              void* d_out, int out_size) {
    const float* x  = (const float*)d_in[0];
    const float* Wq = (const float*)d_in[1];
    const float* Wk = (const float*)d_in[2];
    const float* Wv = (const float*)d_in[3];
    const float* Wo = (const float*)d_in[4];
    float* out = (float*)d_out;

    __half *pxf, *pQf, *pKf, *pVf, *pYf, *pWcf, *pWof;
    float2* ptab;
    cudaGetSymbolAddress((void**)&pxf, g_xf);
    cudaGetSymbolAddress((void**)&pQf, g_Qf);
    cudaGetSymbolAddress((void**)&pKf, g_Kf);
    cudaGetSymbolAddress((void**)&pVf, g_Vf);
    cudaGetSymbolAddress((void**)&pYf, g_Yf);
    cudaGetSymbolAddress((void**)&pWcf, g_Wcf);
    cudaGetSymbolAddress((void**)&pWof, g_Wof);
    cudaGetSymbolAddress((void**)&ptab, g_tab);

    cudaFuncSetAttribute(gemm1_kernel, cudaFuncAttributeMaxDynamicSharedMemorySize, G1_SMEM);
    cudaFuncSetAttribute(attn_f16_kernel, cudaFuncAttributeMaxDynamicSharedMemorySize, ATT_SMEM);

    // #1 x -> fp16 + rope table (fused)
    {
        int n4 = (BT_ * E_) / 4;
        int total = n4 + T_ * 32;
        prep_kernel<<<(total + 255) / 256, 256>>>(x, pxf, ptab, n4);
    }
    // #2 fused transpose Wq|Wk|Wv -> fp16 concat
    txpose3_kernel<<<dim3(64, 32, 3), dim3(32, 8)>>>(Wq, Wk, Wv, pWcf);

    // #3 fused QKV projection with in-epilogue RoPE (+ Q pre-scale)
    gemm1_kernel<<<dim3(NQKV / 128, BT_ / 128), 128, G1_SMEM>>>(
        nullptr, pQf, pKf, pVf, ptab, pxf, pWcf, BT_, NQKV, E_, 1);

    // #4 attention (ncu capture target)
    attn_f16_kernel<<<dim3(T_ / 128, H_, B_), 256, ATT_SMEM>>>(pYf, pQf, pKf, pVf);

    // #5 transpose Wo -> fp16
    txpose_kernel<<<dim3(64, 32), dim3(32, 8)>>>(Wo, pWof, E_, E_, 0);

    // #6 output projection, single-term fp16
    gemm1_kernel<<<dim3(E_ / 128, BT_ / 128), 128, G1_SMEM>>>(
        out, nullptr, nullptr, nullptr, nullptr, pYf, pWof, BT_, E_, E_, 0);
}

// round 15
// speedup vs baseline: 1.0680x; 1.0238x over previous
#include <cuda_runtime.h>
#include <cuda_bf16.h>
#include <cuda_fp16.h>
#include <cstdint>
#include <math.h>

// Problem constants
#define B_  2
#define T_  2048
#define E_  2048
#define H_  32
#define HKV_ 8
#define D_  64
#define BT_ (B_*T_)  // 4096
#define NQKV 3072    // 2048 Q + 512 K + 512 V

// scale * log2(e): folded into Q at projection time; attention uses ex2 directly
#define QSCALE 0.1803368801111357f   // 0.125 * 1.4426950408889634

// ---------------------------------------------------------------------------
// Scratch (static device globals — allocation-free rule)
// ---------------------------------------------------------------------------
__device__ __half g_xf[BT_ * E_];               // x in fp16
__device__ __half g_Qf[BT_ * H_ * D_];          // post-rope, pre-scaled Q fp16
__device__ __half g_Kf[BT_ * HKV_ * D_];        // post-rope K fp16
__device__ __half g_Vf[BT_ * HKV_ * D_];
__device__ __half g_Yf[BT_ * E_];               // attention output fp16
__device__ __half g_Wcf[NQKV * E_];             // concat Wq|Wk|Wv transposed [N,K] fp16
__device__ __half g_Wof[E_ * E_];               // Wo transposed fp16
__device__ float2 g_tab[T_ * 32];               // rope cos/sin table

// ---------------------------------------------------------------------------
// PTX helpers
// ---------------------------------------------------------------------------
__device__ __forceinline__ uint32_t smem_u32(const void* p) {
    uint32_t a;
    asm("{ .reg .u64 t; cvta.to.shared.u64 t, %1; cvt.u32.u64 %0, t; }" : "=r"(a) : "l"(p));
    return a;
}
__device__ __forceinline__ void ldmx4(uint32_t* r, uint32_t addr) {
    asm volatile("ldmatrix.sync.aligned.m8n8.x4.shared.b16 {%0,%1,%2,%3}, [%4];"
                 : "=r"(r[0]), "=r"(r[1]), "=r"(r[2]), "=r"(r[3]) : "r"(addr));
}
__device__ __forceinline__ void ldmx4t(uint32_t* r, uint32_t addr) {
    asm volatile("ldmatrix.sync.aligned.m8n8.x4.trans.shared.b16 {%0,%1,%2,%3}, [%4];"
                 : "=r"(r[0]), "=r"(r[1]), "=r"(r[2]), "=r"(r[3]) : "r"(addr));
}
__device__ __forceinline__ void mma_f16(float* acc, const uint32_t* a, const uint32_t b0,
                                        const uint32_t b1) {
    asm volatile(
        "mma.sync.aligned.m16n8k16.row.col.f32.f16.f16.f32 "
        "{%0,%1,%2,%3}, {%4,%5,%6,%7}, {%8,%9}, {%0,%1,%2,%3};"
        : "+f"(acc[0]), "+f"(acc[1]), "+f"(acc[2]), "+f"(acc[3])
        : "r"(a[0]), "r"(a[1]), "r"(a[2]), "r"(a[3]), "r"(b0), "r"(b1));
}
__device__ __forceinline__ void cp_async16(uint32_t saddr, const void* gaddr) {
    asm volatile("cp.async.cg.shared.global [%0], [%1], 16;" :: "r"(saddr), "l"(gaddr));
}
#define CP_COMMIT() asm volatile("cp.async.commit_group;" ::: "memory")
#define CP_WAIT(n)  asm volatile("cp.async.wait_group %0;" :: "n"(n) : "memory")

__device__ __forceinline__ uint32_t pack_h2(float lo, float hi) {
    __half2 v = __floats2half2_rn(lo, hi);
    return *reinterpret_cast<uint32_t*>(&v);
}
__device__ __forceinline__ float ex2f(float x) {
    float y;
    asm("ex2.approx.f32 %0, %1;" : "=f"(y) : "f"(x));
    return y;
}

// ---------------------------------------------------------------------------
// gemm1: single-term fp16 GEMM, BK=64, 2-stage cp.async, race-safe ordering.
// (unchanged from round 14 — runs at ~89% of the mma.sync issue ceiling)
// ---------------------------------------------------------------------------
#define ROWB   144
#define REGB   (128 * ROWB)          // 18432 per region (128 rows x 64 halves)
#define G1_STG (2 * REGB)            // A + B = 36864
#define G1_SMEM (2 * G1_STG)         // 73728 (double buffered)

__device__ __forceinline__ void g1_issue(uint32_t sbuf, const __half* a, const __half* b,
                                         int K, int tid) {
    const __half* srcs[2] = {a, b};
#pragma unroll
    for (int reg = 0; reg < 2; ++reg) {
        const __half* s = srcs[reg];
        uint32_t sr = sbuf + reg * REGB;
#pragma unroll
        for (int j = 0; j < 8; ++j) {
            int c = tid + j * 128;          // 0..1023
            int row = c >> 3, part = c & 7;
            cp_async16(sr + row * ROWB + part * 16, s + (size_t)row * K + part * 8);
        }
    }
}

__global__ __launch_bounds__(128, 3)
void gemm1_kernel(float* __restrict__ C,
                  __half* __restrict__ Oq, __half* __restrict__ Ok, __half* __restrict__ Ov,
                  const float2* __restrict__ tab,
                  const __half* __restrict__ A, const __half* __restrict__ B,
                  int M, int N, int K, int mode) {
    extern __shared__ char smem[];
    const uint32_t sbase = smem_u32(smem);
    const int tid = threadIdx.x;
    const int wid = tid >> 5, lane = tid & 31;
    const int warp_m = wid >> 1;
    const int warp_n = wid & 1;
    const int bm = blockIdx.y * 128, bn = blockIdx.x * 128;

    const __half* pA = A + (size_t)bm * K;
    const __half* pB = B + (size_t)bn * K;

    float acc[4][8][4];
#pragma unroll
    for (int i = 0; i < 4; ++i)
#pragma unroll
        for (int j = 0; j < 8; ++j)
#pragma unroll
            for (int k = 0; k < 4; ++k) acc[i][j][k] = 0.0f;

    const int NIT = K / 64;

    const uint32_t a_row = warp_m * 64 + (lane & 15);
    const uint32_t a_coff = (lane >> 4) * 16;
    const uint32_t b_rowbase = warp_n * 64 + (lane & 15);
    const uint32_t b_coff = (lane >> 4) * 16;

    g1_issue(sbase, pA, pB, K, tid);
    CP_COMMIT();

    int buf = 0;
    for (int it = 0; it < NIT; ++it) {
        CP_WAIT(0);
        __syncthreads();
        if (it + 1 < NIT) {
            g1_issue(sbase + (buf ^ 1) * G1_STG,
                     pA + (it + 1) * 64, pB + (it + 1) * 64, K, tid);
            CP_COMMIT();
        }

        const uint32_t sbuf = sbase + buf * G1_STG;
        const uint32_t sA = sbuf, sB = sbuf + REGB;
#pragma unroll
        for (int ks = 0; ks < 4; ++ks) {
            const uint32_t kb = ks * 32;
            uint32_t bf[16];
#pragma unroll
            for (int p = 0; p < 4; ++p) {
                uint32_t ba = (b_rowbase + p * 16) * ROWB + kb + b_coff;
                ldmx4(&bf[p * 4], sB + ba);
            }
            uint32_t af[4][4];
#pragma unroll
            for (int mi = 0; mi < 4; ++mi) {
                uint32_t aa = (a_row + mi * 16) * ROWB + kb + a_coff;
                ldmx4(af[mi], sA + aa);
            }
#pragma unroll
            for (int mi = 0; mi < 4; ++mi)
#pragma unroll
                for (int ni = 0; ni < 8; ++ni) {
                    const int p = ni >> 1, q = ni & 1;
                    mma_f16(acc[mi][ni], af[mi], bf[p * 4 + q], bf[p * 4 + q + 2]);
                }
        }
        buf ^= 1;
    }

    const int rbase = bm + warp_m * 64 + (lane >> 2);
    const int j0 = (lane & 3) * 2;
    const int ch = bn + warp_n * 64;

    if (mode == 0) {
        const int cbase = ch + j0;
#pragma unroll
        for (int mi = 0; mi < 4; ++mi)
#pragma unroll
            for (int ni = 0; ni < 8; ++ni) {
                float* c0 = C + (size_t)(rbase + mi * 16) * N + cbase + ni * 8;
                float* c1 = C + (size_t)(rbase + mi * 16 + 8) * N + cbase + ni * 8;
                *(float2*)c0 = make_float2(acc[mi][ni][0], acc[mi][ni][1]);
                *(float2*)c1 = make_float2(acc[mi][ni][2], acc[mi][ni][3]);
            }
        return;
    }

    if (ch < 2560) {
        __half* dst;
        int ldc, cofs;
        float sc;
        if (ch < 2048) { dst = Oq; ldc = H_ * D_;  cofs = ch;        sc = QSCALE; }
        else           { dst = Ok; ldc = HKV_ * D_; cofs = ch - 2048; sc = 1.0f; }
#pragma unroll
        for (int mi = 0; mi < 4; ++mi) {
#pragma unroll
            for (int hf = 0; hf < 2; ++hf) {
                const int r = rbase + mi * 16 + hf * 8;
                const int t = r & (T_ - 1);
                const float2* trow = tab + t * 32;
#pragma unroll
                for (int ni0 = 0; ni0 < 4; ++ni0) {
                    const int j = j0 + ni0 * 8;
                    float a1 = acc[mi][ni0][2 * hf + 0];
                    float a2 = acc[mi][ni0][2 * hf + 1];
                    float b1 = acc[mi][ni0 + 4][2 * hf + 0];
                    float b2 = acc[mi][ni0 + 4][2 * hf + 1];
                    float2 cs1 = trow[j];
                    float2 cs2 = trow[j + 1];
                    float o1 = (a1 * cs1.x - b1 * cs1.y) * sc;
                    float p1 = (b1 * cs1.x + a1 * cs1.y) * sc;
                    float o2 = (a2 * cs2.x - b2 * cs2.y) * sc;
                    float p2 = (b2 * cs2.x + a2 * cs2.y) * sc;
                    size_t base = (size_t)r * ldc + cofs + j;
                    *(uint32_t*)&dst[base]      = pack_h2(o1, o2);
                    *(uint32_t*)&dst[base + 32] = pack_h2(p1, p2);
                }
            }
        }
    } else {
        const int cbase = ch - 2560 + j0;
#pragma unroll
        for (int mi = 0; mi < 4; ++mi)
#pragma unroll
            for (int ni = 0; ni < 8; ++ni) {
                *(uint32_t*)&Ov[(size_t)(rbase + mi * 16) * 512 + cbase + ni * 8] =
                    pack_h2(acc[mi][ni][0], acc[mi][ni][1]);
                *(uint32_t*)&Ov[(size_t)(rbase + mi * 16 + 8) * 512 + cbase + ni * 8] =
                    pack_h2(acc[mi][ni][2], acc[mi][ni][3]);
            }
    }
}

// ---------------------------------------------------------------------------
// prep: x fp32 -> fp16 (vectorized) AND rope table, one launch
// ---------------------------------------------------------------------------
__global__ __launch_bounds__(256)
void prep_kernel(const float* __restrict__ in, __half* __restrict__ out,
                 float2* __restrict__ tab, int n4) {
    int i = blockIdx.x * blockDim.x + threadIdx.x;
    if (i < n4) {
        float4 v = ((const float4*)in)[i];
        ((uint2*)out)[i] = make_uint2(pack_h2(v.x, v.y), pack_h2(v.z, v.w));
    } else {
        int idx = i - n4;
        if (idx < T_ * 32) {
            int k = idx & 31, t = idx >> 5;
            float inv_freq = expf(-(float)k * (9.210340371976184f / 32.0f));
            float ang = (float)t * inv_freq;
            tab[idx] = make_float2(cosf(ang), sinf(ang));
        }
    }
}

// ---------------------------------------------------------------------------
// Vectorized transpose W[K,N] fp32 -> Tf[N,K] fp16, h2-packed stores.
// ---------------------------------------------------------------------------
__global__ __launch_bounds__(256)
void txpose_kernel(const float* __restrict__ W, __half* __restrict__ Tf,
                   int K, int N, int nofs) {
    __shared__ float t[64][33];
    const int tx = threadIdx.x, ty = threadIdx.y;
    const int n0 = blockIdx.x * 32, k0 = blockIdx.y * 64;
#pragma unroll
    for (int i = 0; i < 8; ++i)
        t[ty + i * 8][tx] = W[(size_t)(k0 + ty + i * 8) * N + n0 + tx];
    __syncthreads();
#pragma unroll
    for (int i = 0; i < 4; ++i) {
        int n = ty + i * 8;
        uint32_t v = pack_h2(t[2 * tx][n], t[2 * tx + 1][n]);
        *(uint32_t*)&Tf[(size_t)(nofs + n0 + n) * K + k0 + 2 * tx] = v;
    }
}

__global__ __launch_bounds__(256)
void txpose3_kernel(const float* __restrict__ Wq, const float* __restrict__ Wk,
                    const float* __restrict__ Wv, __half* __restrict__ Tf) {
    __shared__ float t[64][33];
    const int z = blockIdx.z;
    const float* W = (z == 0) ? Wq : (z == 1) ? Wk : Wv;
    const int N = (z == 0) ? (H_ * D_) : (HKV_ * D_);
    const int nofs = (z == 0) ? 0 : (z == 1) ? 2048 : 2560;
    const int n0 = blockIdx.x * 32, k0 = blockIdx.y * 64;
    if (n0 >= N) return;
    const int tx = threadIdx.x, ty = threadIdx.y;
#pragma unroll
    for (int i = 0; i < 8; ++i)
        t[ty + i * 8][tx] = W[(size_t)(k0 + ty + i * 8) * N + n0 + tx];
    __syncthreads();
#pragma unroll
    for (int i = 0; i < 4; ++i) {
        int n = ty + i * 8;
        uint32_t v = pack_h2(t[2 * tx][n], t[2 * tx + 1][n]);
        *(uint32_t*)&Tf[(size_t)(nofs + n0 + n) * E_ + k0 + 2 * tx] = v;
    }
}

// ---------------------------------------------------------------------------
// FA2-style causal attention, fp16 mma.sync, wide warp tiles (M=32/warp).
// 128 threads = 4 warps; warp w owns rows [qb*128 + w*32, +32).
// Each K/V ldmatrix.x4 now feeds 4 MMAs (was 2) -> crossbar traffic halved.
// __launch_bounds__(128, 2): 2 CTAs/SM.
// ---------------------------------------------------------------------------
#define AROWB 144
#define KVREG (64 * AROWB)              // 9216
#define KVBUF (2 * KVREG)               // 18432
#define QREG  (128 * AROWB)             // 18432
#define ATT_SMEM (QREG + 2 * KVBUF)     // 55296

__global__ __launch_bounds__(128, 2)
void attn_f16_kernel(__half* __restrict__ Yf,
                     const __half* __restrict__ Qf, const __half* __restrict__ Kf,
                     const __half* __restrict__ Vf) {
    extern __shared__ char smem[];
    const uint32_t sbase = smem_u32(smem);
    const uint32_t sQ = sbase;
    const uint32_t sKV = sbase + QREG;

    const int tid = threadIdx.x;
    const int wid = tid >> 5, lane = tid & 31;
    const int qb = gridDim.x - 1 - blockIdx.x;    // reversed: big tiles first
    const int h  = blockIdx.y;
    const int b  = blockIdx.z;
    const int kh = h >> 2;
    const int bT0 = b * T_;

    const int rw = qb * 128 + wid * 32;           // warp's first q row
    int row0[2], row1[2];
#pragma unroll
    for (int mi = 0; mi < 2; ++mi) {
        row0[mi] = rw + mi * 16 + (lane >> 2);
        row1[mi] = row0[mi] + 8;
    }
    const int rowmax_w = rw + 31;

    // Q tile: 128 rows x 64 halves (1024 16B chunks / 128 threads)
#pragma unroll
    for (int j = 0; j < 8; ++j) {
        int c = tid + j * 128;
        int row = c >> 3, part = c & 7;
        cp_async16(sQ + row * AROWB + part * 16,
                   Qf + (size_t)(bT0 + qb * 128 + row) * (H_ * D_) + h * 64 + part * 8);
    }
    // KV tile 0 (1024 chunks / 128 threads)
#pragma unroll
    for (int j = 0; j < 8; ++j) {
        int c = tid + j * 128;
        int reg = c >> 9, idx = c & 511;
        int row = idx >> 3, part = idx & 7;
        const __half* src = reg ? Vf : Kf;
        cp_async16(sKV + reg * KVREG + row * AROWB + part * 16,
                   src + (size_t)(bT0 + row) * (HKV_ * D_) + kh * 64 + part * 8);
    }
    CP_COMMIT();
    CP_WAIT(0);
    __syncthreads();

    uint32_t qf[2][4][4];
#pragma unroll
    for (int mi = 0; mi < 2; ++mi)
#pragma unroll
        for (int ks = 0; ks < 4; ++ks) {
            uint32_t qa = (wid * 32 + mi * 16 + (lane & 15)) * AROWB + ks * 32 + (lane >> 4) * 16;
            ldmx4(qf[mi][ks], sQ + qa);
        }

    float o[2][8][4];
#pragma unroll
    for (int mi = 0; mi < 2; ++mi)
#pragma unroll
        for (int j = 0; j < 8; ++j)
#pragma unroll
            for (int k = 0; k < 4; ++k) o[mi][j][k] = 0.0f;
    float mm[2][2], ll[2][2];
#pragma unroll
    for (int mi = 0; mi < 2; ++mi) {
        mm[mi][0] = -1e30f; mm[mi][1] = -1e30f;
        ll[mi][0] = 0.0f;   ll[mi][1] = 0.0f;
    }

    const int NT = 2 * qb + 2;
    int buf = 0;
    for (int it = 0; it < NT; ++it) {
        CP_WAIT(0);
        __syncthreads();
        if (it + 1 < NT) {
            uint32_t sb = sKV + (buf ^ 1) * KVBUF;
#pragma unroll
            for (int j = 0; j < 8; ++j) {
                int c = tid + j * 128;
                int reg = c >> 9, idx = c & 511;
                int row = idx >> 3, part = idx & 7;
                const __half* src = reg ? Vf : Kf;
                cp_async16(sb + reg * KVREG + row * AROWB + part * 16,
                           src + (size_t)(bT0 + (it + 1) * 64 + row) * (HKV_ * D_) + kh * 64 + part * 8);
            }
            CP_COMMIT();
        }

        const int kt = it;
        if (kt * 64 <= rowmax_w) {
            const uint32_t sb = sKV + buf * KVBUF;
            const uint32_t sK = sb, sV = sb + KVREG;

            float s[2][8][4];
#pragma unroll
            for (int mi = 0; mi < 2; ++mi)
#pragma unroll
                for (int j = 0; j < 8; ++j)
#pragma unroll
                    for (int k = 0; k < 4; ++k) s[mi][j][k] = 0.0f;

#pragma unroll
            for (int ks = 0; ks < 4; ++ks) {
#pragma unroll
                for (int pg = 0; pg < 2; ++pg) {
                    uint32_t kf[2][4];
#pragma unroll
                    for (int pp = 0; pp < 2; ++pp) {
                        uint32_t ka = ((2 * pg + pp) * 16 + (lane & 15)) * AROWB + ks * 32 + (lane >> 4) * 16;
                        ldmx4(kf[pp], sK + ka);
                    }
#pragma unroll
                    for (int pp = 0; pp < 2; ++pp)
#pragma unroll
                        for (int mi = 0; mi < 2; ++mi)
#pragma unroll
                            for (int q = 0; q < 2; ++q)
                                mma_f16(s[mi][(2 * pg + pp) * 2 + q], qf[mi][ks],
                                        kf[pp][q], kf[pp][q + 2]);
                }
            }

            // mask (logits already log2-scaled via Q)
            const bool needs_mask = (kt * 64 + 63) > rw;
            if (needs_mask) {
#pragma unroll
                for (int mi = 0; mi < 2; ++mi)
#pragma unroll
                    for (int j = 0; j < 8; ++j) {
                        int colb = kt * 64 + j * 8 + 2 * (lane & 3);
                        if (colb > row0[mi])     s[mi][j][0] = -1e30f;
                        if (colb + 1 > row0[mi]) s[mi][j][1] = -1e30f;
                        if (colb > row1[mi])     s[mi][j][2] = -1e30f;
                        if (colb + 1 > row1[mi]) s[mi][j][3] = -1e30f;
                    }
            }

#pragma unroll
            for (int mi = 0; mi < 2; ++mi) {
                float mx0 = -1e30f, mx1 = -1e30f;
#pragma unroll
                for (int j = 0; j < 8; ++j) {
                    mx0 = fmaxf(mx0, fmaxf(s[mi][j][0], s[mi][j][1]));
                    mx1 = fmaxf(mx1, fmaxf(s[mi][j][2], s[mi][j][3]));
                }
                mx0 = fmaxf(mx0, __shfl_xor_sync(0xFFFFFFFF, mx0, 1));
                mx0 = fmaxf(mx0, __shfl_xor_sync(0xFFFFFFFF, mx0, 2));
                mx1 = fmaxf(mx1, __shfl_xor_sync(0xFFFFFFFF, mx1, 1));
                mx1 = fmaxf(mx1, __shfl_xor_sync(0xFFFFFFFF, mx1, 2));

                float mn0 = fmaxf(mm[mi][0], mx0), mn1 = fmaxf(mm[mi][1], mx1);
                float c0 = ex2f(mm[mi][0] - mn0), c1 = ex2f(mm[mi][1] - mn1);
                mm[mi][0] = mn0; mm[mi][1] = mn1;
                ll[mi][0] *= c0; ll[mi][1] *= c1;
#pragma unroll
                for (int j = 0; j < 8; ++j) {
                    o[mi][j][0] *= c0; o[mi][j][1] *= c0;
                    o[mi][j][2] *= c1; o[mi][j][3] *= c1;
                }
#pragma unroll
                for (int j = 0; j < 8; ++j) {
                    s[mi][j][0] = ex2f(s[mi][j][0] - mn0);
                    s[mi][j][1] = ex2f(s[mi][j][1] - mn0);
                    s[mi][j][2] = ex2f(s[mi][j][2] - mn1);
                    s[mi][j][3] = ex2f(s[mi][j][3] - mn1);
                    ll[mi][0] += s[mi][j][0] + s[mi][j][1];
                    ll[mi][1] += s[mi][j][2] + s[mi][j][3];
                }
            }

#pragma unroll
            for (int ks = 0; ks < 4; ++ks) {
                uint32_t pa[2][4];
#pragma unroll
                for (int mi = 0; mi < 2; ++mi) {
                    pa[mi][0] = pack_h2(s[mi][2 * ks][0], s[mi][2 * ks][1]);
                    pa[mi][1] = pack_h2(s[mi][2 * ks][2], s[mi][2 * ks][3]);
                    pa[mi][2] = pack_h2(s[mi][2 * ks + 1][0], s[mi][2 * ks + 1][1]);
                    pa[mi][3] = pack_h2(s[mi][2 * ks + 1][2], s[mi][2 * ks + 1][3]);
                }
#pragma unroll
                for (int pg = 0; pg < 2; ++pg) {
                    uint32_t vf[2][4];
#pragma unroll
                    for (int pp = 0; pp < 2; ++pp) {
                        uint32_t va = (ks * 16 + (lane & 15)) * AROWB + (2 * pg + pp) * 32 + (lane >> 4) * 16;
                        ldmx4t(vf[pp], sV + va);
                    }
#pragma unroll
                    for (int pp = 0; pp < 2; ++pp)
#pragma unroll
                        for (int mi = 0; mi < 2; ++mi)
#pragma unroll
                            for (int q = 0; q < 2; ++q)
                                mma_f16(o[mi][(2 * pg + pp) * 2 + q], pa[mi],
                                        vf[pp][2 * q], vf[pp][2 * q + 1]);
                }
            }
        }
        buf ^= 1;
    }

#pragma unroll
    for (int mi = 0; mi < 2; ++mi) {
        ll[mi][0] += __shfl_xor_sync(0xFFFFFFFF, ll[mi][0], 1);
        ll[mi][0] += __shfl_xor_sync(0xFFFFFFFF, ll[mi][0], 2);
        ll[mi][1] += __shfl_xor_sync(0xFFFFFFFF, ll[mi][1], 1);
        ll[mi][1] += __shfl_xor_sync(0xFFFFFFFF, ll[mi][1], 2);
        float inv0 = 1.0f / ll[mi][0], inv1 = 1.0f / ll[mi][1];

#pragma unroll
        for (int j = 0; j < 8; ++j) {
            int col = j * 8 + 2 * (lane & 3);
            size_t a0 = ((size_t)(bT0 + row0[mi]) * H_ + h) * 64 + col;
            size_t a1 = ((size_t)(bT0 + row1[mi]) * H_ + h) * 64 + col;
            *(uint32_t*)&Yf[a0] = pack_h2(o[mi][j][0] * inv0, o[mi][j][1] * inv0);
            *(uint32_t*)&Yf[a1] = pack_h2(o[mi][j][2] * inv1, o[mi][j][3] * inv1);
        }
    }
}

// ---------------------------------------------------------------------------
// kernel_launch — attention is our 4th launch (ncu capture target)
// ---------------------------------------------------------------------------
extern "C" void kernel_launch(void* const* d_in, const int* in_sizes, int n_in,
                              void* d_out, int out_size) {
    const float* x  = (const float*)d_in[0];
    const float* Wq = (const float*)d_in[1];
    const float* Wk = (const float*)d_in[2];
    const float* Wv = (const float*)d_in[3];
    const float* Wo = (const float*)d_in[4];
    float* out = (float*)d_out;

    __half *pxf, *pQf, *pKf, *pVf, *pYf, *pWcf, *pWof;
    float2* ptab;
    cudaGetSymbolAddress((void**)&pxf, g_xf);
    cudaGetSymbolAddress((void**)&pQf, g_Qf);
    cudaGetSymbolAddress((void**)&pKf, g_Kf);
    cudaGetSymbolAddress((void**)&pVf, g_Vf);
    cudaGetSymbolAddress((void**)&pYf, g_Yf);
    cudaGetSymbolAddress((void**)&pWcf, g_Wcf);
    cudaGetSymbolAddress((void**)&pWof, g_Wof);
    cudaGetSymbolAddress((void**)&ptab, g_tab);

    cudaFuncSetAttribute(gemm1_kernel, cudaFuncAttributeMaxDynamicSharedMemorySize, G1_SMEM);
    cudaFuncSetAttribute(attn_f16_kernel, cudaFuncAttributeMaxDynamicSharedMemorySize, ATT_SMEM);

    // #1 x -> fp16 + rope table (fused)
    {
        int n4 = (BT_ * E_) / 4;
        int total = n4 + T_ * 32;
        prep_kernel<<<(total + 255) / 256, 256>>>(x, pxf, ptab, n4);
    }
    // #2 fused transpose Wq|Wk|Wv -> fp16 concat
    txpose3_kernel<<<dim3(64, 32, 3), dim3(32, 8)>>>(Wq, Wk, Wv, pWcf);

    // #3 fused QKV projection with in-epilogue RoPE (+ Q pre-scale)
    gemm1_kernel<<<dim3(NQKV / 128, BT_ / 128), 128, G1_SMEM>>>(
        nullptr, pQf, pKf, pVf, ptab, pxf, pWcf, BT_, NQKV, E_, 1);

    // #4 attention (ncu capture target) — 128 threads, M=32 warp tiles
    attn_f16_kernel<<<dim3(T_ / 128, H_, B_), 128, ATT_SMEM>>>(pYf, pQf, pKf, pVf);

    // #5 transpose Wo -> fp16
    txpose_kernel<<<dim3(64, 32), dim3(32, 8)>>>(Wo, pWof, E_, E_, 0);

    // #6 output projection, single-term fp16
    gemm1_kernel<<<dim3(E_ / 128, BT_ / 128), 128, G1_SMEM>>>(
        out, nullptr, nullptr, nullptr, nullptr, pYf, pWof, BT_, E_, E_, 0);
}